// round 8
// baseline (speedup 1.0000x reference)
#include <cuda_runtime.h>

// Problem constants (fixed shapes from setup_inputs)
#define HD 256
#define WD 256
#define HS 128
#define WS 128
#define C1CH 512
#define KD 64
#define COUT 256
#define NB 2
#define PSRC (HS*WS)      // 16384
#define PDST (HD*WD)      // 65536

// Scratch (static device globals — no runtime allocation)
__device__ float g_Kbuf[NB*KD*PSRC];      // K = W2@c2+b2, transposed layout [kk][x*128+y]
__device__ float g_M[NB*C1CH*PSRC];       // M = W1^T K,  transposed layout [c][x*128+y]
__device__ float g_T[NB*PSRC];            // T = b1^T K,  transposed layout
__device__ float g_att[NB*PDST*4];        // softmax(energy)*coef per dest pixel
__device__ float g_outT[NB*COUT*PSRC];    // transposed 'out'

// ---------------- f32x2 helpers (packed dual-FP32 FMA) ----------------
__device__ __forceinline__ unsigned long long bcast2(float a) {
    unsigned long long r;
    asm("mov.b64 %0, {%1, %1};" : "=l"(r) : "f"(a));
    return r;
}
__device__ __forceinline__ void ffma2(unsigned long long& d,
                                      unsigned long long a,
                                      unsigned long long b) {
    asm("fma.rn.f32x2 %0, %1, %2, %0;" : "+l"(d) : "l"(a), "l"(b));
}
__device__ __forceinline__ float2 unpack2(unsigned long long v) {
    float2 f;
    asm("mov.b64 {%0, %1}, %2;" : "=f"(f.x), "=f"(f.y) : "l"(v));
    return f;
}

// ---------------- Kernel T: transpose out [h][w] -> out_t [w][h] ----------------
__global__ void transpose_out_kernel(const float* __restrict__ out) {
    __shared__ float tile[32][33];
    int bc = blockIdx.z;                       // b*COUT + c
    const float* src = out + (size_t)bc * PSRC;
    float*       dst = g_outT + (size_t)bc * PSRC;
    int h0 = blockIdx.y * 32, w0 = blockIdx.x * 32;
    int tx = threadIdx.x;
    #pragma unroll
    for (int i = threadIdx.y; i < 32; i += 8)
        tile[i][tx] = src[(size_t)(h0 + i) * WS + w0 + tx];
    __syncthreads();
    #pragma unroll
    for (int i = threadIdx.y; i < 32; i += 8)
        dst[(size_t)(w0 + i) * HS + h0 + tx] = tile[tx][i];
}

// ---------------- Kernel A1: Kbuf_t = W2 @ c2 + b2 (M=64,K=512,N=16384 per batch) ----
// Block: one src h-row (128 natural-j columns), 256 threads, 8kk x 4j micro-tile (f32x2).
// smem: 8.7KB + 16KB = 24.7KB
__global__ void __launch_bounds__(256) gemmK_kernel(const float* __restrict__ c2,
                                                    const float* __restrict__ W2,
                                                    const float* __restrict__ b2) {
    __shared__ __align__(16) float As[32][68];   // As[k][kk], row 272B (16B-mult)
    __shared__ __align__(16) float Bs[32][128];  // Bs[k][j]
    int b  = blockIdx.y;
    int jt = blockIdx.x;                         // == src row h
    int tid = threadIdx.x;
    int tx = tid & 31, ty = tid >> 5;
    int kk0 = ty * 8;

    unsigned long long acc[8][2];
    #pragma unroll
    for (int i = 0; i < 8; i++) { acc[i][0] = 0ull; acc[i][1] = 0ull; }

    const float* c2p = c2 + (size_t)b * C1CH * PSRC + (size_t)jt * 128;

    for (int k0 = 0; k0 < C1CH; k0 += 32) {
        // load W2 chunk transposed: As[k][kk] = W2[kk][k0+k]
        for (int idx = tid; idx < 64 * 32; idx += 256) {
            int kk = idx >> 5, k = idx & 31;
            As[k][kk] = W2[kk * C1CH + k0 + k];
        }
        // load c2 chunk: Bs[k][j]
        for (int idx = tid; idx < 1024; idx += 256) {
            int r = idx >> 5, c4 = idx & 31;
            *(float4*)&Bs[r][c4 * 4] =
                *(const float4*)&c2p[(size_t)(k0 + r) * PSRC + c4 * 4];
        }
        __syncthreads();
        #pragma unroll
        for (int k = 0; k < 32; k++) {
            float4 a0 = *(const float4*)&As[k][kk0];
            float4 a1 = *(const float4*)&As[k][kk0 + 4];
            unsigned long long bA = *(const unsigned long long*)&Bs[k][2 * tx];
            unsigned long long bB = *(const unsigned long long*)&Bs[k][64 + 2 * tx];
            unsigned long long p;
            p = bcast2(a0.x); ffma2(acc[0][0], p, bA); ffma2(acc[0][1], p, bB);
            p = bcast2(a0.y); ffma2(acc[1][0], p, bA); ffma2(acc[1][1], p, bB);
            p = bcast2(a0.z); ffma2(acc[2][0], p, bA); ffma2(acc[2][1], p, bB);
            p = bcast2(a0.w); ffma2(acc[3][0], p, bA); ffma2(acc[3][1], p, bB);
            p = bcast2(a1.x); ffma2(acc[4][0], p, bA); ffma2(acc[4][1], p, bB);
            p = bcast2(a1.y); ffma2(acc[5][0], p, bA); ffma2(acc[5][1], p, bB);
            p = bcast2(a1.z); ffma2(acc[6][0], p, bA); ffma2(acc[6][1], p, bB);
            p = bcast2(a1.w); ffma2(acc[7][0], p, bA); ffma2(acc[7][1], p, bB);
        }
        __syncthreads();
    }
    // epilogue: +bias, store TRANSPOSED: Kbuf_t[kk][w*128 + h]
    float* kb = g_Kbuf + (size_t)b * KD * PSRC;
    #pragma unroll
    for (int i = 0; i < 8; i++) {
        float bias = b2[kk0 + i];
        #pragma unroll
        for (int l = 0; l < 2; l++) {
            float2 v = unpack2(acc[i][l]);
            int w = l * 64 + 2 * tx;
            kb[(size_t)(kk0 + i) * PSRC + (size_t)w * HS + jt]       = v.x + bias;
            kb[(size_t)(kk0 + i) * PSRC + (size_t)(w + 1) * HS + jt] = v.y + bias;
        }
    }
}

// ---------------- Kernel A2: M_t = W1^T @ Kbuf_t (M=512,K=64,N=16384), + T = b1^T Kbuf_t
// K chunked into 2x32 so smem = 8KB + 16KB = 24KB (static-smem limit is 48KB).
__global__ void __launch_bounds__(256) gemmM_kernel(const float* __restrict__ W1,
                                                    const float* __restrict__ b1) {
    __shared__ __align__(16) float As[32][64];   // As[k][cc] = W1[k0+k][c0+cc]
    __shared__ __align__(16) float Bs[32][128];  // Bs[k][j']
    int b  = blockIdx.z;
    int ct = blockIdx.y;
    int jt = blockIdx.x;
    int c0 = ct * 64;
    int tid = threadIdx.x;
    int tx = tid & 31, ty = tid >> 5;
    int cc0 = ty * 8;

    const float* kb = g_Kbuf + (size_t)b * KD * PSRC + (size_t)jt * 128;

    unsigned long long acc[8][2];
    #pragma unroll
    for (int i = 0; i < 8; i++) { acc[i][0] = 0ull; acc[i][1] = 0ull; }
    float Tacc = 0.f;

    for (int k0 = 0; k0 < KD; k0 += 32) {
        // load W1 chunk: As[k][cc] = W1[(k0+k)*C1CH + c0+cc]
        for (int idx = tid; idx < 512; idx += 256) {
            int k = idx >> 4, c4 = idx & 15;
            *(float4*)&As[k][c4 * 4] =
                *(const float4*)&W1[(size_t)(k0 + k) * C1CH + c0 + c4 * 4];
        }
        // load Kbuf chunk: Bs[k][j]
        for (int idx = tid; idx < 1024; idx += 256) {
            int r = idx >> 5, c4 = idx & 31;
            *(float4*)&Bs[r][c4 * 4] =
                *(const float4*)&kb[(size_t)(k0 + r) * PSRC + c4 * 4];
        }
        __syncthreads();

        #pragma unroll
        for (int k = 0; k < 32; k++) {
            float4 a0 = *(const float4*)&As[k][cc0];
            float4 a1 = *(const float4*)&As[k][cc0 + 4];
            unsigned long long bA = *(const unsigned long long*)&Bs[k][2 * tx];
            unsigned long long bB = *(const unsigned long long*)&Bs[k][64 + 2 * tx];
            unsigned long long p;
            p = bcast2(a0.x); ffma2(acc[0][0], p, bA); ffma2(acc[0][1], p, bB);
            p = bcast2(a0.y); ffma2(acc[1][0], p, bA); ffma2(acc[1][1], p, bB);
            p = bcast2(a0.z); ffma2(acc[2][0], p, bA); ffma2(acc[2][1], p, bB);
            p = bcast2(a0.w); ffma2(acc[3][0], p, bA); ffma2(acc[3][1], p, bB);
            p = bcast2(a1.x); ffma2(acc[4][0], p, bA); ffma2(acc[4][1], p, bB);
            p = bcast2(a1.y); ffma2(acc[5][0], p, bA); ffma2(acc[5][1], p, bB);
            p = bcast2(a1.z); ffma2(acc[6][0], p, bA); ffma2(acc[6][1], p, bB);
            p = bcast2(a1.w); ffma2(acc[7][0], p, bA); ffma2(acc[7][1], p, bB);
        }
        // T = b1^T Kbuf (only one ct-slice needs it; use this chunk's Bs while live)
        if (ct == 0 && tid < 128) {
            #pragma unroll
            for (int k = 0; k < 32; k++)
                Tacc += __ldg(&b1[k0 + k]) * Bs[k][tid];
        }
        __syncthreads();
    }

    #pragma unroll
    for (int i = 0; i < 8; i++) {
        float* Mp = g_M + (size_t)(b * C1CH + c0 + cc0 + i) * PSRC + (size_t)jt * 128;
        *(float2*)&Mp[2 * tx]      = unpack2(acc[i][0]);
        *(float2*)&Mp[64 + 2 * tx] = unpack2(acc[i][1]);
    }
    if (ct == 0 && tid < 128)
        g_T[b * PSRC + jt * 128 + tid] = Tacc;
}

// ---------------- Kernel B: energy (c1 . M) + T, softmax*coef -> att --------------
// One block per (dest row dX, batch). 256 threads: two 128-thread halves each
// reduce 256 of the 512 channels for dest pixels (2t, 2t+1); combined via smem.
__global__ void __launch_bounds__(256) energy_kernel(const float* __restrict__ c1) {
    __shared__ float red[8][128];
    int b = blockIdx.y, dX = blockIdx.x;
    int tid = threadIdx.x;
    int t = tid & 127, half = tid >> 7;

    float sx = (dX + 0.5f) * 0.5f - 0.5f;
    int x0  = (int)floorf(sx);
    int x1  = (x0 + 1 < HS - 1) ? x0 + 1 : HS - 1;
    int x00 = x0 > 0 ? x0 : 0;

    float sya = (2 * t + 0.5f) * 0.5f - 0.5f;         // = t - 0.25
    float syb = (2 * t + 1 + 0.5f) * 0.5f - 0.5f;     // = t + 0.25
    int y0a = (int)floorf(sya);
    int y1a = (y0a + 1 < WS - 1) ? y0a + 1 : WS - 1;
    int y00a = y0a > 0 ? y0a : 0;
    int y0b = (int)floorf(syb);
    int y1b = (y0b + 1 < WS - 1) ? y0b + 1 : WS - 1;
    int y00b = y0b > 0 ? y0b : 0;
    // identities for these shapes: y00a = max(t-1,0), y1a = y00b = t, y1b = min(t+1,127)
    int yA = y00a, yB = y1a, yC = y1b;

    int cbase = half * (C1CH / 2);
    const float* M0 = g_M + (size_t)(b * C1CH + cbase) * PSRC + (size_t)x00 * HS;
    const float* M1 = g_M + (size_t)(b * C1CH + cbase) * PSRC + (size_t)x1 * HS;
    const float* q  = c1 + (size_t)(b * C1CH + cbase) * PDST + (size_t)dX * WD + 2 * t;

    float e0 = 0, e1 = 0, e2 = 0, e3 = 0, e4 = 0, e5 = 0, e6 = 0, e7 = 0;
    #pragma unroll 4
    for (int c = 0; c < C1CH / 2; c++) {
        float2 qq = *(const float2*)(q + (size_t)c * PDST);
        const float* m0 = M0 + (size_t)c * PSRC;
        const float* m1 = M1 + (size_t)c * PSRC;
        float ma0 = m0[yA], mb0 = m0[yB], mc0 = m0[yC];
        float ma1 = m1[yA], mb1 = m1[yB], mc1 = m1[yC];
        e0 += qq.x * ma0; e1 += qq.x * mb0; e2 += qq.x * ma1; e3 += qq.x * mb1;
        e4 += qq.y * mb0; e5 += qq.y * mc0; e6 += qq.y * mb1; e7 += qq.y * mc1;
    }
    if (half == 1) {
        red[0][t] = e0; red[1][t] = e1; red[2][t] = e2; red[3][t] = e3;
        red[4][t] = e4; red[5][t] = e5; red[6][t] = e6; red[7][t] = e7;
    }
    __syncthreads();
    if (half == 1) return;
    e0 += red[0][t]; e1 += red[1][t]; e2 += red[2][t]; e3 += red[3][t];
    e4 += red[4][t]; e5 += red[5][t]; e6 += red[6][t]; e7 += red[7][t];

    const float* T0 = g_T + b * PSRC + x00 * HS;
    const float* T1 = g_T + b * PSRC + x1 * HS;
    e0 += T0[y00a]; e1 += T0[y1a]; e2 += T1[y00a]; e3 += T1[y1a];
    e4 += T0[y00b]; e5 += T0[y1b]; e6 += T1[y00b]; e7 += T1[y1b];

    float dx0 = sx - (float)x0;
    float dx1 = (float)x1 - sx;
    float* attp = g_att + ((size_t)b * PDST + (size_t)dX * WD + 2 * t) * 4;

    {   // pixel A (dY = 2t)
        float dy0 = sya - (float)y0a, dy1 = (float)y1a - sya;
        float nrm = (float)((x1 - x0) * (y1a - y0a));
        if (nrm == 0.f) nrm = 1.f;
        float inv_n = 1.f / nrm;
        float c0 = dx0 * dy0 * inv_n, c1c = dx0 * dy1 * inv_n;
        float c2c = dx1 * dy0 * inv_n, c3 = dx1 * dy1 * inv_n;
        float mx = fmaxf(fmaxf(e0, e1), fmaxf(e2, e3));
        float x0e = __expf(e0 - mx), x1e = __expf(e1 - mx);
        float x2e = __expf(e2 - mx), x3e = __expf(e3 - mx);
        float inv = 1.f / (x0e + x1e + x2e + x3e);
        float4 a = make_float4(x0e * inv * c0, x1e * inv * c1c,
                               x2e * inv * c2c, x3e * inv * c3);
        *(float4*)attp = a;
    }
    {   // pixel B (dY = 2t+1)
        float dy0 = syb - (float)y0b, dy1 = (float)y1b - syb;
        float nrm = (float)((x1 - x0) * (y1b - y0b));
        if (nrm == 0.f) nrm = 1.f;
        float inv_n = 1.f / nrm;
        float c0 = dx0 * dy0 * inv_n, c1c = dx0 * dy1 * inv_n;
        float c2c = dx1 * dy0 * inv_n, c3 = dx1 * dy1 * inv_n;
        float mx = fmaxf(fmaxf(e4, e5), fmaxf(e6, e7));
        float x0e = __expf(e4 - mx), x1e = __expf(e5 - mx);
        float x2e = __expf(e6 - mx), x3e = __expf(e7 - mx);
        float inv = 1.f / (x0e + x1e + x2e + x3e);
        float4 a = make_float4(x0e * inv * c0, x1e * inv * c1c,
                               x2e * inv * c2c, x3e * inv * c3);
        *(float4*)(attp + 4) = a;
    }
}

// ---------------- Kernel C: res[c][p] = sum_k out_t[c][s'_k] * att[p][k] ----------
// 256 threads: two 128-thread halves each handle 128 of the 256 channels
// (channels independent — no reduction needed).
__global__ void __launch_bounds__(256) apply_kernel(float* __restrict__ res) {
    int b = blockIdx.y, dX = blockIdx.x;
    int tid = threadIdx.x;
    int t = tid & 127, half = tid >> 7;

    float sx = (dX + 0.5f) * 0.5f - 0.5f;
    int x0  = (int)floorf(sx);
    int x1  = (x0 + 1 < HS - 1) ? x0 + 1 : HS - 1;
    int x00 = x0 > 0 ? x0 : 0;
    int yA = t - 1 > 0 ? t - 1 : 0;
    int yB = t;
    int yC = t + 1 < WS - 1 ? t + 1 : WS - 1;

    const float* attp = g_att + ((size_t)b * PDST + (size_t)dX * WD + 2 * t) * 4;
    float4 aA = *(const float4*)attp;
    float4 aB = *(const float4*)(attp + 4);

    int cbase = half * (COUT / 2);
    const float* O0 = g_outT + (size_t)(b * COUT + cbase) * PSRC + (size_t)x00 * HS;
    const float* O1 = g_outT + (size_t)(b * COUT + cbase) * PSRC + (size_t)x1 * HS;
    float* r = res + (size_t)(b * COUT + cbase) * PDST + (size_t)dX * WD + 2 * t;

    #pragma unroll 4
    for (int c = 0; c < COUT / 2; c++) {
        const float* o0 = O0 + (size_t)c * PSRC;
        const float* o1 = O1 + (size_t)c * PSRC;
        float ma0 = o0[yA], mb0 = o0[yB], mc0 = o0[yC];
        float ma1 = o1[yA], mb1 = o1[yB], mc1 = o1[yC];
        float rA = aA.x * ma0 + aA.y * mb0 + aA.z * ma1 + aA.w * mb1;
        float rB = aB.x * mb0 + aB.y * mc0 + aB.z * mb1 + aB.w * mc1;
        *(float2*)(r + (size_t)c * PDST) = make_float2(rA, rB);
    }
}

// -------------------------------- launch --------------------------------
extern "C" void kernel_launch(void* const* d_in, const int* in_sizes, int n_in,
                              void* d_out, int out_size) {
    const float* c1 = (const float*)d_in[0];
    const float* c2 = (const float*)d_in[1];
    const float* out = (const float*)d_in[2];
    const float* W1 = (const float*)d_in[3];
    const float* b1 = (const float*)d_in[4];
    const float* W2 = (const float*)d_in[5];
    const float* b2 = (const float*)d_in[6];
    float* res = (float*)d_out;

    transpose_out_kernel<<<dim3(4, 4, NB * COUT), dim3(32, 8)>>>(out);
    gemmK_kernel<<<dim3(PSRC / 128, NB), 256>>>(c2, W2, b2);
    gemmM_kernel<<<dim3(PSRC / 128, C1CH / 64, NB), 256>>>(W1, b1);
    energy_kernel<<<dim3(HD, NB), 256>>>(c1);
    apply_kernel<<<dim3(HD, NB), 256>>>(res);
}